// round 7
// baseline (speedup 1.0000x reference)
#include <cuda_runtime.h>
#include <cuda_fp16.h>
#include <math.h>

#define CC    10
#define NN    1152
#define DIN   8
#define DOUT  16
#define BB    256
#define THREADS 512
#define NWARPS  16
#define KPT     9      // nodes per thread: NN / (THREADS/4)

typedef unsigned long long ull;

// Transposed fp16 weights: [c][i][n][o]  (2.95 MB scratch, written each launch)
__device__ __half g_Wh[CC * DIN * NN * DOUT];

// ---- packed f32x2 helpers (Blackwell FFMA2 — PTX-only, ptxas won't auto-fuse) ----
__device__ __forceinline__ ull pack2(float lo, float hi) {
    ull r; asm("mov.b64 %0, {%1, %2};" : "=l"(r) : "f"(lo), "f"(hi)); return r;
}
__device__ __forceinline__ float2 unpack2(ull v) {
    float2 f; asm("mov.b64 {%0, %1}, %2;" : "=f"(f.x), "=f"(f.y) : "l"(v)); return f;
}
__device__ __forceinline__ ull fma2(ull a, ull b, ull c) {
    ull d; asm("fma.rn.f32x2 %0, %1, %2, %3;" : "=l"(d) : "l"(a), "l"(b), "l"(c)); return d;
}
__device__ __forceinline__ ull add2(ull a, ull b) {
    ull d; asm("add.rn.f32x2 %0, %1, %2;" : "=l"(d) : "l"(a), "l"(b)); return d;
}
// half2 (lo,hi) -> packed f32x2 (lo,hi)
__device__ __forceinline__ ull h2_to_f32x2(unsigned int h2) {
    ull d;
    asm("{\n\t"
        ".reg .f16 h0, h1;\n\t"
        ".reg .f32 f0, f1;\n\t"
        "mov.b32 {h0, h1}, %1;\n\t"
        "cvt.f32.f16 f0, h0;\n\t"
        "cvt.f32.f16 f1, h1;\n\t"
        "mov.b64 %0, {f0, f1};\n\t"
        "}" : "=l"(d) : "r"(h2));
    return d;
}

// ------- W transpose + fp16 convert: [c][n][i][o] f32 -> [c][i][n][o] f16 -------
__global__ void transpose_W_kernel(const float4* __restrict__ W4) {
    __shared__ float4 tile[1024];              // 16 KB
    uint2* Wh8 = reinterpret_cast<uint2*>(g_Wh);   // 8B = 4 halves
    const int c  = blockIdx.x / (NN / 32);
    const int n0 = (blockIdx.x % (NN / 32)) * 32;
    const int tid = threadIdx.x;               // 256

    const int in_base = (c * NN + n0) * 32;    // 32 float4 per node row
#pragma unroll
    for (int k = 0; k < 4; ++k)
        tile[tid + k * 256] = W4[in_base + tid + k * 256];
    __syncthreads();
#pragma unroll
    for (int k = 0; k < 4; ++k) {
        int j  = tid + k * 256;                // 0..1023 over output order
        int i  = j >> 7;                       // 0..7
        int nn = (j >> 2) & 31;                // 0..31
        int q  = j & 3;                        // 4-half quad within o-dim
        float4 v = tile[nn * 32 + i * 4 + q];
        __half2 a = __floats2half2_rn(v.x, v.y);   // lo = v.x
        __half2 b = __floats2half2_rn(v.z, v.w);
        uint2 o;
        o.x = *reinterpret_cast<unsigned int*>(&a);
        o.y = *reinterpret_cast<unsigned int*>(&b);
        Wh8[((c * DIN + i) * NN + n0 + nn) * 4 + q] = o;
    }
}

// ---------- fused priors + routing; BT=1, 2 CTAs/SM for latency hiding ----------
__global__ __launch_bounds__(THREADS, 2)
void caps_routing_kernel(const float* __restrict__ x,
                         float* __restrict__ out) {
    __shared__ float  red[16 * NWARPS];        // per-warp o-partials
    __shared__ float  redw_se[NWARPS];         // per-warp exp-sum partials
    __shared__ float4 outv4[4];                // out vector, 16B aligned

    const int tid  = threadIdx.x;
    const int lane = tid & 31;
    const int wid  = tid >> 5;
    const int oq   = tid & 3;                  // o-quad: owns o = oq*4 .. oq*4+3
    const int g    = tid >> 2;                 // node group 0..127
    const int c    = blockIdx.x;
    const int b    = blockIdx.y;

    const uint2* Wh8 = reinterpret_cast<const uint2*>(g_Wh);
    float* outv = reinterpret_cast<float*>(outv4);

    // ===== Phase 1: priors into registers (f32x2 o-pairs) + iter-0 sum =====
    ull pri2[KPT][2];                          // lanes = (o, o+1)
    ull s02[2] = {0ull, 0ull};

#pragma unroll
    for (int k = 0; k < KPT; ++k) {
        const int n = g + 128 * k;
        const float4* xr = reinterpret_cast<const float4*>(x + (b * NN + n) * DIN);
        float4 v0 = xr[0], v1 = xr[1];
        float xa[8];
        xa[0]=v0.x; xa[1]=v0.y; xa[2]=v0.z; xa[3]=v0.w;
        xa[4]=v1.x; xa[5]=v1.y; xa[6]=v1.z; xa[7]=v1.w;

        ull a0 = 0ull, a1 = 0ull;
#pragma unroll
        for (int i = 0; i < 8; ++i) {
            // warp reads 256B contiguous fp16: lanes = (8 consecutive n) x (4 o-quads)
            uint2 w = Wh8[((c * DIN + i) * NN + n) * 4 + oq];
            ull b01 = h2_to_f32x2(w.x);
            ull b23 = h2_to_f32x2(w.y);
            ull xs  = pack2(xa[i], xa[i]);
            a0 = fma2(xs, b01, a0);
            a1 = fma2(xs, b23, a1);
        }
        pri2[k][0] = a0;
        pri2[k][1] = a1;
        s02[0] = add2(s02[0], a0);
        s02[1] = add2(s02[1], a1);
    }

    // unpack iter-0 partial sums, reduce over the 8 node-groups per warp
    float s0[4];
    {
        float2 a = unpack2(s02[0]), bb = unpack2(s02[1]);
        s0[0] = a.x; s0[1] = a.y; s0[2] = bb.x; s0[3] = bb.y;
    }
    for (int m = 4; m < 32; m <<= 1)
#pragma unroll
        for (int j = 0; j < 4; ++j)
            s0[j] += __shfl_xor_sync(0xffffffffu, s0[j], m);
    if (lane < 4)
#pragma unroll
        for (int j = 0; j < 4; ++j)
            red[(lane * 4 + j) * NWARPS + wid] = s0[j];
    __syncthreads();

    // iter-0 finalize: s = mean over n, squash
    // NOTE: only lanes 0..15 of warp 0 participate -> mask MUST be 0xffff.
    if (tid < 16) {
        const int o = tid;
        float s = 0.0f;
#pragma unroll
        for (int w = 0; w < NWARPS; ++w) s += red[o * NWARPS + w];
        s *= (1.0f / (float)NN);
        float q = s * s;
        for (int m = 1; m < 16; m <<= 1) q += __shfl_xor_sync(0xffffu, q, m);
        float scale = q / ((1.0f + q) * sqrtf(q));
        outv[o] = scale * s;
    }

    // ===== Routing iterations 1..2 (logits persistent in registers) =====
    float lg[KPT];
#pragma unroll
    for (int k = 0; k < KPT; ++k) lg[k] = 0.0f;

    for (int it = 0; it < 2; ++it) {
        __syncthreads();

        // out vector o-pairs for this thread's quad (8B-aligned smem reads)
        const ull* ovp = reinterpret_cast<const ull*>(outv + oq * 4);
        ull ov0 = ovp[0];
        ull ov1 = ovp[1];

        // agreement: lg[n] += priors[n,:] . out   (no max pass — exp is safe:
        // |logit| <= sum_iter ||pri_row||*||out||, and squash keeps ||out||<1)
#pragma unroll
        for (int k = 0; k < KPT; ++k) {
            ull d2 = fma2(pri2[k][0], ov0, fma2(pri2[k][1], ov1, 0ull));
            float2 dd = unpack2(d2);
            float d = dd.x + dd.y;
            d += __shfl_xor_sync(0xffffffffu, d, 1);
            d += __shfl_xor_sync(0xffffffffu, d, 2);
            lg[k] += d;
        }

        // exp + fused weighted-sum with UNNORMALIZED weights
        ull sp20 = 0ull, sp21 = 0ull;
        float se = 0.0f;
#pragma unroll
        for (int k = 0; k < KPT; ++k) {
            float e = __expf(lg[k]);
            se += e;
            ull e2 = pack2(e, e);
            sp20 = fma2(e2, pri2[k][0], sp20);
            sp21 = fma2(e2, pri2[k][1], sp21);
        }
        float sp[4];
        {
            float2 a = unpack2(sp20), bb = unpack2(sp21);
            sp[0] = a.x; sp[1] = a.y; sp[2] = bb.x; sp[3] = bb.y;
        }
        // se: full-warp reduce (4x redundancy across oq -> exactly 4*true)
        for (int m = 1; m < 32; m <<= 1)
            se += __shfl_xor_sync(0xffffffffu, se, m);
        // sp: reduce across node-groups only (keep oq distinct)
        for (int m = 4; m < 32; m <<= 1)
#pragma unroll
            for (int j = 0; j < 4; ++j)
                sp[j] += __shfl_xor_sync(0xffffffffu, sp[j], m);
        if (lane == 0) redw_se[wid] = se;
        if (lane < 4)
#pragma unroll
            for (int j = 0; j < 4; ++j)
                red[(lane * 4 + j) * NWARPS + wid] = sp[j];
        __syncthreads();

        // finalize: normalize, squash, write (lanes 0..15 only -> mask 0xffff)
        if (tid < 16) {
            const int o = tid;
            float sps = 0.0f, ses = 0.0f;
#pragma unroll
            for (int w = 0; w < NWARPS; ++w) {
                sps += red[o * NWARPS + w];
                ses += redw_se[w];
            }
            float s = sps * (4.0f / ses);     // /4 undoes oq redundancy exactly
            float q = s * s;
            for (int m = 1; m < 16; m <<= 1) q += __shfl_xor_sync(0xffffu, q, m);
            float scale = q / ((1.0f + q) * sqrtf(q));
            float o_ = scale * s;
            outv[o] = o_;
            if (it == 1)
                out[((size_t)c * BB + b) * DOUT + o] = o_;
        }
    }
}

extern "C" void kernel_launch(void* const* d_in, const int* in_sizes, int n_in,
                              void* d_out, int out_size) {
    const float* x = (const float*)d_in[0];   // [256,1152,8]
    const float* W = (const float*)d_in[1];   // [10,1152,8,16]
    float* out = (float*)d_out;               // [10,256,1,16]

    transpose_W_kernel<<<CC * (NN / 32), 256>>>(reinterpret_cast<const float4*>(W));

    dim3 grid(CC, BB);
    caps_routing_kernel<<<grid, THREADS>>>(x, out);
}

// round 8
// speedup vs baseline: 1.0810x; 1.0810x over previous
#include <cuda_runtime.h>
#include <cuda_fp16.h>
#include <math.h>

#define CC    10
#define NN    1152
#define DIN   8
#define DOUT  16
#define BB    256

typedef unsigned long long ull;

// fp16 W, same [c][n][i][o] layout (2.95 MB)
__device__ __half g_Wh[CC * NN * DIN * DOUT];
// fp16 priors [c][b][n][o] (94.4 MB scratch)
__device__ __half g_pri[(size_t)CC * BB * NN * DOUT];

// ---- packed f32x2 helpers (Blackwell FFMA2 — PTX-only) ----
__device__ __forceinline__ ull pack2(float lo, float hi) {
    ull r; asm("mov.b64 %0, {%1, %2};" : "=l"(r) : "f"(lo), "f"(hi)); return r;
}
__device__ __forceinline__ float2 unpack2(ull v) {
    float2 f; asm("mov.b64 {%0, %1}, %2;" : "=f"(f.x), "=f"(f.y) : "l"(v)); return f;
}
__device__ __forceinline__ ull fma2(ull a, ull b, ull c) {
    ull d; asm("fma.rn.f32x2 %0, %1, %2, %3;" : "=l"(d) : "l"(a), "l"(b), "l"(c)); return d;
}
__device__ __forceinline__ ull add2(ull a, ull b) {
    ull d; asm("add.rn.f32x2 %0, %1, %2;" : "=l"(d) : "l"(a), "l"(b)); return d;
}
// half2 (lo,hi) -> packed f32x2 (lo,hi)
__device__ __forceinline__ ull h2_to_f32x2(unsigned int h2) {
    ull d;
    asm("{\n\t"
        ".reg .f16 h0, h1;\n\t"
        ".reg .f32 f0, f1;\n\t"
        "mov.b32 {h0, h1}, %1;\n\t"
        "cvt.f32.f16 f0, h0;\n\t"
        "cvt.f32.f16 f1, h1;\n\t"
        "mov.b64 %0, {f0, f1};\n\t"
        "}" : "=l"(d) : "r"(h2));
    return d;
}
// packed f32x2 (lo,hi) -> half2 (lo,hi)    cvt.rn.f16x2.f32 d, HI, LO
__device__ __forceinline__ unsigned int f32x2_to_h2(ull v) {
    unsigned int r;
    asm("{\n\t"
        ".reg .f32 lo, hi;\n\t"
        "mov.b64 {lo, hi}, %1;\n\t"
        "cvt.rn.f16x2.f32 %0, hi, lo;\n\t"
        "}" : "=r"(r) : "l"(v));
    return r;
}

// ================= Kernel 1: W fp32 -> fp16 (same layout) =================
__global__ void convert_W(const float4* __restrict__ W4) {
    int j = blockIdx.x * 256 + threadIdx.x;     // 368640 float4s total
    float4 v = W4[j];
    __half2 a = __floats2half2_rn(v.x, v.y);    // lo = v.x
    __half2 b = __floats2half2_rn(v.z, v.w);
    uint2 o;
    o.x = *reinterpret_cast<unsigned int*>(&a);
    o.y = *reinterpret_cast<unsigned int*>(&b);
    reinterpret_cast<uint2*>(g_Wh)[j] = o;
}

// ================= Kernel 2: priors GEMM -> g_pri (fp16) =================
// grid (CC, 9, 16); 128 threads; thread owns node n, loops 16 batch elems.
__global__ __launch_bounds__(128)
void priors_kernel(const float* __restrict__ x) {
    const int tid = threadIdx.x;
    const int c  = blockIdx.x;
    const int n  = blockIdx.y * 128 + tid;
    const int b0 = blockIdx.z * 16;

    // Load + convert this node's W row ONCE: 128 halves -> 64 f32x2 regs.
    // w2[i*8+p] = (W[c,n,i,2p], W[c,n,i,2p+1])
    const uint4* wp = reinterpret_cast<const uint4*>(g_Wh) + ((size_t)c * NN + n) * 16;
    ull w2[64];
#pragma unroll
    for (int m = 0; m < 16; ++m) {
        uint4 q = wp[m];
        int base = (m >> 1) * 8 + (m & 1) * 4;
        w2[base + 0] = h2_to_f32x2(q.x);
        w2[base + 1] = h2_to_f32x2(q.y);
        w2[base + 2] = h2_to_f32x2(q.z);
        w2[base + 3] = h2_to_f32x2(q.w);
    }

    uint4* op = reinterpret_cast<uint4*>(g_pri);

#pragma unroll 2
    for (int bb = 0; bb < 16; ++bb) {
        const int b = b0 + bb;
        const float4* xr = reinterpret_cast<const float4*>(x + ((size_t)b * NN + n) * DIN);
        float4 v0 = xr[0], v1 = xr[1];
        float xa[8];
        xa[0]=v0.x; xa[1]=v0.y; xa[2]=v0.z; xa[3]=v0.w;
        xa[4]=v1.x; xa[5]=v1.y; xa[6]=v1.z; xa[7]=v1.w;

        ull acc[8];
#pragma unroll
        for (int p = 0; p < 8; ++p) acc[p] = 0ull;
#pragma unroll
        for (int i = 0; i < 8; ++i) {
            ull xs = pack2(xa[i], xa[i]);
#pragma unroll
            for (int p = 0; p < 8; ++p)
                acc[p] = fma2(xs, w2[i * 8 + p], acc[p]);
        }
        uint4 o0, o1;
        o0.x = f32x2_to_h2(acc[0]); o0.y = f32x2_to_h2(acc[1]);
        o0.z = f32x2_to_h2(acc[2]); o0.w = f32x2_to_h2(acc[3]);
        o1.x = f32x2_to_h2(acc[4]); o1.y = f32x2_to_h2(acc[5]);
        o1.z = f32x2_to_h2(acc[6]); o1.w = f32x2_to_h2(acc[7]);
        size_t oi = ((size_t)(c * BB + b) * NN + n) * 2;
        op[oi]     = o0;
        op[oi + 1] = o1;
    }
}

// ================= Kernel 3: routing, priors tile in SMEM =================
// grid (CC, BB); 256 threads (8 warps); 4 CTAs/SM.
#define T3    256
#define NW3   8
#define KPT3  18   // nodes per thread: NN / (T3/4)

__global__ __launch_bounds__(T3, 4)
void routing_kernel(float* __restrict__ out) {
    __shared__ __align__(16) __half spri[NN * DOUT];   // 36864 B
    __shared__ float red[16 * NW3];
    __shared__ float sew[NW3];
    __shared__ __align__(16) float outv[16];

    const int tid  = threadIdx.x;
    const int lane = tid & 31;
    const int wid  = tid >> 5;
    const int oq   = tid & 3;     // owns o = oq*4 .. oq*4+3
    const int g    = tid >> 2;    // node group 0..63
    const int c    = blockIdx.x;
    const int b    = blockIdx.y;

    // ---- load priors tile: 2304 x 16B, fully coalesced ----
    {
        const uint4* src = reinterpret_cast<const uint4*>(g_pri) + (size_t)(c * BB + b) * NN * 2;
        uint4* dst = reinterpret_cast<uint4*>(spri);
#pragma unroll
        for (int t = 0; t < 9; ++t)
            dst[tid + t * T3] = src[tid + t * T3];
    }
    __syncthreads();

    // ---- iter 0: uniform weights -> s = mean over n, squash ----
    {
        ull s0 = 0ull, s1 = 0ull;
#pragma unroll
        for (int k = 0; k < KPT3; ++k) {
            const uint2 h = *reinterpret_cast<const uint2*>(&spri[(g + 64 * k) * 16 + oq * 4]);
            s0 = add2(s0, h2_to_f32x2(h.x));
            s1 = add2(s1, h2_to_f32x2(h.y));
        }
        float s[4];
        { float2 a = unpack2(s0), bb2 = unpack2(s1);
          s[0]=a.x; s[1]=a.y; s[2]=bb2.x; s[3]=bb2.y; }
        for (int m = 4; m < 32; m <<= 1)
#pragma unroll
            for (int j = 0; j < 4; ++j)
                s[j] += __shfl_xor_sync(0xffffffffu, s[j], m);
        if (lane < 4)
#pragma unroll
            for (int j = 0; j < 4; ++j)
                red[(lane * 4 + j) * NW3 + wid] = s[j];
    }
    __syncthreads();
    if (tid < 16) {
        const int o = tid;
        float s = 0.0f;
#pragma unroll
        for (int w = 0; w < NW3; ++w) s += red[o * NW3 + w];
        s *= (1.0f / (float)NN);
        float q = s * s;
        for (int m = 1; m < 16; m <<= 1) q += __shfl_xor_sync(0xffffu, q, m);
        float scale = q / ((1.0f + q) * sqrtf(q));
        outv[o] = scale * s;
    }

    // ---- iterations 1..2: fused agreement + exp + weighted sum ----
    float lg[KPT3];
#pragma unroll
    for (int k = 0; k < KPT3; ++k) lg[k] = 0.0f;

    for (int it = 1; it <= 2; ++it) {
        __syncthreads();
        const ull* ovp = reinterpret_cast<const ull*>(outv) + oq * 2;
        const ull ov0 = ovp[0];
        const ull ov1 = ovp[1];

        ull sp0 = 0ull, sp1 = 0ull;
        float se = 0.0f;
#pragma unroll
        for (int k = 0; k < KPT3; ++k) {
            const uint2 h = *reinterpret_cast<const uint2*>(&spri[(g + 64 * k) * 16 + oq * 4]);
            const ull p0 = h2_to_f32x2(h.x);
            const ull p1 = h2_to_f32x2(h.y);
            // agreement (no max pass — exp safe since ||out||<1 bounds logits)
            ull d2 = fma2(p0, ov0, fma2(p1, ov1, 0ull));
            float2 dd = unpack2(d2);
            float d = dd.x + dd.y;
            d += __shfl_xor_sync(0xffffffffu, d, 1);
            d += __shfl_xor_sync(0xffffffffu, d, 2);
            lg[k] += d;
            // unnormalized softmax weight + weighted sum
            float e = __expf(lg[k]);
            se += e;
            ull e2 = pack2(e, e);
            sp0 = fma2(e2, p0, sp0);
            sp1 = fma2(e2, p1, sp1);
        }
        float sp[4];
        { float2 a = unpack2(sp0), bb2 = unpack2(sp1);
          sp[0]=a.x; sp[1]=a.y; sp[2]=bb2.x; sp[3]=bb2.y; }
        // se: full-warp reduce (4x oq redundancy -> exactly 4*true)
        for (int m = 1; m < 32; m <<= 1)
            se += __shfl_xor_sync(0xffffffffu, se, m);
        // sp: reduce across node-groups only (keep oq distinct)
        for (int m = 4; m < 32; m <<= 1)
#pragma unroll
            for (int j = 0; j < 4; ++j)
                sp[j] += __shfl_xor_sync(0xffffffffu, sp[j], m);
        if (lane == 0) sew[wid] = se;
        if (lane < 4)
#pragma unroll
            for (int j = 0; j < 4; ++j)
                red[(lane * 4 + j) * NW3 + wid] = sp[j];
        __syncthreads();

        if (tid < 16) {
            const int o = tid;
            float sps = 0.0f, ses = 0.0f;
#pragma unroll
            for (int w = 0; w < NW3; ++w) {
                sps += red[o * NW3 + w];
                ses += sew[w];
            }
            float s = sps * (4.0f / ses);   // /4 undoes oq redundancy exactly
            float q = s * s;
            for (int m = 1; m < 16; m <<= 1) q += __shfl_xor_sync(0xffffu, q, m);
            float scale = q / ((1.0f + q) * sqrtf(q));
            float o_ = scale * s;
            outv[o] = o_;
            if (it == 2)
                out[((size_t)c * BB + b) * DOUT + o] = o_;
        }
    }
}

extern "C" void kernel_launch(void* const* d_in, const int* in_sizes, int n_in,
                              void* d_out, int out_size) {
    const float* x = (const float*)d_in[0];   // [256,1152,8]
    const float* W = (const float*)d_in[1];   // [10,1152,8,16]
    float* out = (float*)d_out;               // [10,256,1,16]

    convert_W<<<1440, 256>>>(reinterpret_cast<const float4*>(W));

    dim3 g2(CC, NN / 128, BB / 16);           // (10, 9, 16)
    priors_kernel<<<g2, 128>>>(x);

    dim3 g3(CC, BB);                          // (10, 256)
    routing_kernel<<<g3, T3>>>(out);
}